// round 7
// baseline (speedup 1.0000x reference)
#include <cuda_runtime.h>
#include <cuda_bf16.h>
#include <cstdint>

#define NN   16384
#define HID  256
#define NEMAX 1048576
#define ETOT (NEMAX + NN)

// ---------------- device scratch ----------------
__device__ float g_h1[(size_t)NN * HID];
__device__ float g_h2[(size_t)NN * HID];
__device__ int   g_deg[NN];
__device__ float g_dinv[NN];
__device__ int   g_rowstart[NN + 1];
__device__ int   g_cursor[NN];
__device__ int   g_csr[ETOT];
__device__ float g_sa[NN];
__device__ float g_sb[NN];
__device__ __nv_bfloat16 g_B1[(size_t)512 * NN];
__device__ __nv_bfloat16 g_B2[(size_t)512 * HID];

__device__ __forceinline__ uint32_t smem_u32(const void* p) {
    uint32_t a;
    asm("{ .reg .u64 t; cvta.to.shared.u64 t, %1; cvt.u32.u64 %0, t; }" : "=r"(a) : "l"(p));
    return a;
}
__device__ __forceinline__ void ldm_x4(uint32_t addr, uint32_t* r) {
    asm volatile("ldmatrix.sync.aligned.m8n8.x4.shared.b16 {%0,%1,%2,%3}, [%4];"
                 : "=r"(r[0]), "=r"(r[1]), "=r"(r[2]), "=r"(r[3]) : "r"(addr));
}
__device__ __forceinline__ void mma_bf16(float* c, const uint32_t* a, const uint32_t* b) {
    asm volatile("mma.sync.aligned.m16n8k16.row.col.f32.bf16.bf16.f32 "
                 "{%0,%1,%2,%3}, {%4,%5,%6,%7}, {%8,%9}, {%0,%1,%2,%3};"
                 : "+f"(c[0]), "+f"(c[1]), "+f"(c[2]), "+f"(c[3])
                 : "r"(a[0]), "r"(a[1]), "r"(a[2]), "r"(a[3]), "r"(b[0]), "r"(b[1]));
}
__device__ __forceinline__ void cp16(uint32_t dst, const void* src) {
    asm volatile("cp.async.cg.shared.global [%0], [%1], 16;" :: "r"(dst), "l"(src));
}
#define CP_COMMIT() asm volatile("cp.async.commit_group;" ::: "memory")
#define CP_WAIT0()  asm volatile("cp.async.wait_group 0;" ::: "memory")

// ---------------- weight prep: W[K,256] fp32 -> gB[512,K] bf16 (transposed hi/lo split) ----
__global__ void k_prep_B(const float* __restrict__ W, __nv_bfloat16* __restrict__ gB, int K) {
    __shared__ float tile[32][33];
    int t = threadIdx.x;
    int k0 = blockIdx.x * 32, n0 = blockIdx.y * 32;
#pragma unroll
    for (int p = 0; p < 4; p++) {
        int idx = t + 256 * p, i = idx >> 5, j = idx & 31;
        tile[i][j] = W[(size_t)(k0 + i) * HID + n0 + j];
    }
    __syncthreads();
    int jp = t >> 3, i0 = (t & 7) * 4;
    __nv_bfloat16 hi[4], lo[4];
#pragma unroll
    for (int q = 0; q < 4; q++) {
        float v = tile[i0 + q][jp];
        hi[q] = __float2bfloat16(v);
        lo[q] = __float2bfloat16(v - __bfloat162float(hi[q]));
    }
    *(uint2*)&gB[(size_t)(n0 + jp) * K + k0 + i0]       = *(uint2*)hi;
    *(uint2*)&gB[(size_t)(256 + n0 + jp) * K + k0 + i0] = *(uint2*)lo;
}

// ---------------- HMMA GEMM: CTA tile 256x128, 8 warps (4M x 2N), warp tile 64x64 ----
// Stage: Ahi 256x80B | Alo 256x80B | Bhi 128x80B | Blo 128x80B = 61440B, x2 stages.
#define A_ROWB   80
#define SM_A1    20480
#define SM_B0    40960
#define SM_B1    51200
#define STAGE_BYTES 61440
#define HG_SMEM (2 * STAGE_BYTES)

__global__ __launch_bounds__(256)
void k_hgemm(const float* __restrict__ A, const __nv_bfloat16* __restrict__ gB,
             float* __restrict__ C, int K) {
    extern __shared__ char smem[];
    const uint32_t sb = smem_u32(smem);
    const int t = threadIdx.x;
    const int lane = t & 31, w = t >> 5;
    const int wm = w & 3, wn = w >> 2;          // 4 x 2 warp grid
    const int mo = blockIdx.x * 256;
    const int nb = blockIdx.y * 128;
    const int nc = K / 32;

    // A loader: 1 thread per row, 32 floats (8 float4)
    const int arow = t;
    // B loader: 2 threads per row
    const int brow = t >> 1, bpart = t & 1;

    float4 xa[8];

    auto ldgA = [&](int c) {
        const float* Ap = A + (size_t)(mo + arow) * K + c * 32;
#pragma unroll
        for (int q = 0; q < 8; q++) xa[q] = *(const float4*)(Ap + 4 * q);
    };
    auto cpB = [&](int c, int st) {
        uint32_t dst = sb + st * STAGE_BYTES + SM_B0 + brow * A_ROWB + bpart * 32;
        const __nv_bfloat16* Bp0 = gB + (size_t)(nb + brow) * K + c * 32 + bpart * 16;
        const __nv_bfloat16* Bp1 = gB + (size_t)(256 + nb + brow) * K + c * 32 + bpart * 16;
        cp16(dst, Bp0);
        cp16(dst + 16, Bp0 + 8);
        cp16(dst + (SM_B1 - SM_B0), Bp1);
        cp16(dst + (SM_B1 - SM_B0) + 16, Bp1 + 8);
    };
    auto stsA = [&](int st) {
        char* base = smem + st * STAGE_BYTES;
        __nv_bfloat16 h[32], l[32];
#pragma unroll
        for (int q = 0; q < 8; q++) {
            float v[4] = {xa[q].x, xa[q].y, xa[q].z, xa[q].w};
#pragma unroll
            for (int e = 0; e < 4; e++) {
                h[q * 4 + e] = __float2bfloat16(v[e]);
                l[q * 4 + e] = __float2bfloat16(v[e] - __bfloat162float(h[q * 4 + e]));
            }
        }
        uint32_t aoff = (uint32_t)arow * A_ROWB;
#pragma unroll
        for (int q = 0; q < 4; q++) {
            *(uint4*)(base + aoff + 16 * q)          = *(uint4*)&h[8 * q];
            *(uint4*)(base + SM_A1 + aoff + 16 * q)  = *(uint4*)&l[8 * q];
        }
    };

    float acc[4][8][4];
#pragma unroll
    for (int i = 0; i < 4; i++)
#pragma unroll
        for (int j = 0; j < 8; j++)
#pragma unroll
            for (int e = 0; e < 4; e++) acc[i][j][e] = 0.f;

    const int lm = lane & 7, sel = lane >> 3;
    const uint32_t a_row_off = (uint32_t)(wm * 64 + (sel & 1) * 8 + lm) * A_ROWB + (uint32_t)(sel >> 1) * 16;
    const uint32_t b_row_off = (uint32_t)(wn * 64 + (sel >> 1) * 8 + lm) * A_ROWB + (uint32_t)(sel & 1) * 16;

    // prologue
    cpB(0, 0);
    CP_COMMIT();
    ldgA(0);
    stsA(0);
    CP_WAIT0();
    __syncthreads();

    for (int c = 0; c < nc; c++) {
        const int st = c & 1;
        if (c + 1 < nc) {
            cpB(c + 1, st ^ 1);
            CP_COMMIT();
            ldgA(c + 1);
        }

        const uint32_t stage = sb + st * STAGE_BYTES;
#pragma unroll
        for (int kk = 0; kk < 2; kk++) {
            const uint32_t kb = (uint32_t)kk * 32;
            uint32_t a1[4][4], a2[4][4];
#pragma unroll
            for (int mt = 0; mt < 4; mt++) {
                uint32_t ar = stage + a_row_off + (uint32_t)mt * (16 * A_ROWB) + kb;
                ldm_x4(ar, a1[mt]);
                ldm_x4(ar + SM_A1, a2[mt]);
            }
            uint32_t b1[8][2], b2[8][2];
#pragma unroll
            for (int pr = 0; pr < 4; pr++) {
                uint32_t brd = stage + SM_B0 + b_row_off + (uint32_t)pr * (16 * A_ROWB) + kb;
                uint32_t r[4];
                ldm_x4(brd, r);
                b1[2 * pr][0] = r[0]; b1[2 * pr][1] = r[1];
                b1[2 * pr + 1][0] = r[2]; b1[2 * pr + 1][1] = r[3];
                ldm_x4(brd + (SM_B1 - SM_B0), r);
                b2[2 * pr][0] = r[0]; b2[2 * pr][1] = r[1];
                b2[2 * pr + 1][0] = r[2]; b2[2 * pr + 1][1] = r[3];
            }
            // pass-major: three long HMMA bursts of 32
#pragma unroll
            for (int mt = 0; mt < 4; mt++)
#pragma unroll
                for (int nt = 0; nt < 8; nt++) mma_bf16(acc[mt][nt], a1[mt], b1[nt]);
#pragma unroll
            for (int mt = 0; mt < 4; mt++)
#pragma unroll
                for (int nt = 0; nt < 8; nt++) mma_bf16(acc[mt][nt], a1[mt], b2[nt]);
#pragma unroll
            for (int mt = 0; mt < 4; mt++)
#pragma unroll
                for (int nt = 0; nt < 8; nt++) mma_bf16(acc[mt][nt], a2[mt], b1[nt]);
        }
        if (c + 1 < nc) stsA(st ^ 1);
        CP_WAIT0();
        __syncthreads();
    }

    // epilogue
#pragma unroll
    for (int mt = 0; mt < 4; mt++) {
        int r0 = mo + wm * 64 + mt * 16 + (lane >> 2);
#pragma unroll
        for (int nt = 0; nt < 8; nt++) {
            int cb = nb + wn * 64 + nt * 8 + (lane & 3) * 2;
            float2 v0 = make_float2(acc[mt][nt][0], acc[mt][nt][1]);
            float2 v1 = make_float2(acc[mt][nt][2], acc[mt][nt][3]);
            *(float2*)(C + (size_t)r0 * HID + cb)       = v0;
            *(float2*)(C + (size_t)(r0 + 8) * HID + cb) = v1;
        }
    }
}

// ---------------- degree / CSR construction ----------------
__global__ void k_init_deg() {
    int i = blockIdx.x * blockDim.x + threadIdx.x;
    if (i < NN) g_deg[i] = 1;
}
__global__ void k_count_deg(const int* __restrict__ dst, int E) {
    int i = blockIdx.x * blockDim.x + threadIdx.x;
    if (i < E) atomicAdd(&g_deg[dst[i]], 1);
}
__global__ void k_dinv() {
    int i = blockIdx.x * blockDim.x + threadIdx.x;
    if (i < NN) g_dinv[i] = rsqrtf((float)g_deg[i]);
}
__global__ void k_scan() {
    __shared__ int sh[1024];
    int tid = threadIdx.x;
    int local[16];
    int sum = 0;
#pragma unroll
    for (int i = 0; i < 16; i++) { local[i] = g_deg[tid * 16 + i]; sum += local[i]; }
    sh[tid] = sum;
    __syncthreads();
    for (int off = 1; off < 1024; off <<= 1) {
        int v = (tid >= off) ? sh[tid - off] : 0;
        __syncthreads();
        sh[tid] += v;
        __syncthreads();
    }
    int run = (tid == 0) ? 0 : sh[tid - 1];
#pragma unroll
    for (int i = 0; i < 16; i++) {
        g_rowstart[tid * 16 + i] = run;
        g_cursor[tid * 16 + i]   = run;
        run += local[i];
    }
    if (tid == 1023) g_rowstart[NN] = run;
}
__global__ void k_fill(const int* __restrict__ src, const int* __restrict__ dst, int E) {
    int i = blockIdx.x * blockDim.x + threadIdx.x;
    if (i >= E + NN) return;
    int s, d;
    if (i < E) { s = src[i]; d = dst[i]; }
    else       { s = i - E; d = s; }
    int slot = atomicAdd(&g_cursor[d], 1);
    g_csr[slot] = s;
}
__global__ void k_sort_rows() {
    __shared__ int s[1024];
    int r = blockIdx.x;
    int beg = g_rowstart[r], end = g_rowstart[r + 1];
    int len = end - beg;
    if (len <= 1 || len > 1024) return;
    for (int i = threadIdx.x; i < len; i += blockDim.x) s[i] = g_csr[beg + i];
    __syncthreads();
    for (int ph = 0; ph < len; ph++) {
        int off = ph & 1;
        for (int j = off + 2 * (int)threadIdx.x; j + 1 < len; j += 2 * (int)blockDim.x) {
            int a = s[j], b = s[j + 1];
            if (a > b) { s[j] = b; s[j + 1] = a; }
        }
        __syncthreads();
    }
    for (int i = threadIdx.x; i < len; i += blockDim.x) g_csr[beg + i] = s[i];
}

// ---------------- aggregation ----------------
__global__ void k_agg(const float* __restrict__ hin, float* __restrict__ hout,
                      const float* __restrict__ bias) {
    int v = blockIdx.x;
    int t = threadIdx.x;
    int beg = g_rowstart[v], end = g_rowstart[v + 1];
    float dv = g_dinv[v];
    __shared__ int   ssrc[256];
    __shared__ float snorm[256];
    float acc = 0.f;
    for (int base = beg; base < end; base += 256) {
        int n = min(256, end - base);
        if (t < n) {
            int s = g_csr[base + t];
            ssrc[t]  = s * HID;
            snorm[t] = g_dinv[s] * dv;
        }
        __syncthreads();
        int j = 0;
        for (; j + 4 <= n; j += 4) {
            float x0 = hin[ssrc[j]     + t];
            float x1 = hin[ssrc[j + 1] + t];
            float x2 = hin[ssrc[j + 2] + t];
            float x3 = hin[ssrc[j + 3] + t];
            acc += x0 * snorm[j] + x1 * snorm[j + 1] + x2 * snorm[j + 2] + x3 * snorm[j + 3];
        }
        for (; j < n; j++) acc += hin[ssrc[j] + t] * snorm[j];
        __syncthreads();
    }
    float r = acc + bias[t];
    hout[(size_t)v * HID + t] = r > 0.f ? r : 0.f;
}

// ---------------- edge scoring ----------------
__global__ void k_scores(const float* __restrict__ linW) {
    int v = blockIdx.x, t = threadIdx.x;
    float hv = g_h2[(size_t)v * HID + t];
    __shared__ float sa[256], sb2[256];
    sa[t]  = hv * linW[t];
    sb2[t] = hv * linW[HID + t];
    __syncthreads();
    for (int s = 128; s > 0; s >>= 1) {
        if (t < s) { sa[t] += sa[t + s]; sb2[t] += sb2[t + s]; }
        __syncthreads();
    }
    if (t == 0) { g_sa[v] = sa[0]; g_sb[v] = sb2[0]; }
}
__global__ void k_edge_out(const int* __restrict__ src, const int* __restrict__ dst,
                           const float* __restrict__ linb, float* __restrict__ out, int E) {
    int i = blockIdx.x * blockDim.x + threadIdx.x;
    if (i < E) out[i] = g_sa[src[i]] + g_sb[dst[i]] + linb[0];
}

// ---------------- launch ----------------
extern "C" void kernel_launch(void* const* d_in, const int* in_sizes, int n_in,
                              void* d_out, int out_size) {
    const float* x    = (const float*)d_in[0];
    const int*   ei   = (const int*)d_in[1];
    const float* W1   = (const float*)d_in[2];
    const float* b1   = (const float*)d_in[3];
    const float* W2   = (const float*)d_in[4];
    const float* b2   = (const float*)d_in[5];
    const float* linW = (const float*)d_in[6];
    const float* linb = (const float*)d_in[7];
    float* out = (float*)d_out;

    int E = in_sizes[1] / 2;
    const int* esrc = ei;
    const int* edst = ei + E;

    float *h1, *h2;
    __nv_bfloat16 *B1, *B2;
    cudaGetSymbolAddress((void**)&h1, g_h1);
    cudaGetSymbolAddress((void**)&h2, g_h2);
    cudaGetSymbolAddress((void**)&B1, g_B1);
    cudaGetSymbolAddress((void**)&B2, g_B2);

    cudaFuncSetAttribute(k_hgemm, cudaFuncAttributeMaxDynamicSharedMemorySize, HG_SMEM);

    // launch order arranged so k_hgemm (layer 1) is launch index 3 -> ncu captures it
    k_prep_B<<<dim3(NN / 32, HID / 32), 256>>>(W1, B1, NN);        // 0
    k_prep_B<<<dim3(HID / 32, HID / 32), 256>>>(W2, B2, HID);      // 1
    k_init_deg<<<NN / 256, 256>>>();                               // 2
    k_hgemm<<<dim3(NN / 256, 2), 256, HG_SMEM>>>(x, B1, h1, NN);   // 3 <- profile target

    // graph structure
    k_count_deg<<<(E + 255) / 256, 256>>>(edst, E);
    k_dinv<<<NN / 256, 256>>>();
    k_scan<<<1, 1024>>>();
    k_fill<<<(E + NN + 255) / 256, 256>>>(esrc, edst, E);
    k_sort_rows<<<NN, 256>>>();

    // layer 1 aggregation
    k_agg<<<NN, 256>>>(h1, h2, b1);
    // layer 2
    k_hgemm<<<dim3(NN / 256, 2), 256, HG_SMEM>>>(h2, B2, h1, HID);
    k_agg<<<NN, 256>>>(h1, h2, b2);

    // edge scores
    k_scores<<<NN, 256>>>(linW);
    k_edge_out<<<(E + 255) / 256, 256>>>(esrc, edst, linb, out, E);
}

// round 8
// speedup vs baseline: 1.1138x; 1.1138x over previous
#include <cuda_runtime.h>
#include <cstdint>

#define NN   16384
#define HID  256
#define NEMAX 1048576
#define ETOT (NEMAX + NN)

// ---------------- device scratch ----------------
__device__ float g_h1[(size_t)NN * HID];
__device__ float g_h2[(size_t)NN * HID];
__device__ int   g_deg[NN];
__device__ float g_dinv[NN];
__device__ int   g_rowstart[NN + 1];
__device__ int   g_cursor[NN];
__device__ int   g_csr[ETOT];
__device__ float g_sa[NN];
__device__ float g_sb[NN];
// tf32-rounded transposed weights, [N=256, K] row-major
__device__ float g_B1f[(size_t)HID * NN];
__device__ float g_B2f[(size_t)HID * HID];

__device__ __forceinline__ uint32_t smem_u32(const void* p) {
    uint32_t a;
    asm("{ .reg .u64 t; cvta.to.shared.u64 t, %1; cvt.u32.u64 %0, t; }" : "=r"(a) : "l"(p));
    return a;
}
__device__ __forceinline__ void ldm_x4(uint32_t addr, uint32_t* r) {
    asm volatile("ldmatrix.sync.aligned.m8n8.x4.shared.b16 {%0,%1,%2,%3}, [%4];"
                 : "=r"(r[0]), "=r"(r[1]), "=r"(r[2]), "=r"(r[3]) : "r"(addr));
}
__device__ __forceinline__ uint32_t to_tf32(uint32_t raw) {
    uint32_t o;
    asm("cvt.rna.tf32.f32 %0, %1;" : "=r"(o) : "f"(__uint_as_float(raw)));
    return o;
}
__device__ __forceinline__ void mma_tf32(float* c, const uint32_t* a, const uint32_t* b) {
    asm volatile("mma.sync.aligned.m16n8k8.row.col.f32.tf32.tf32.f32 "
                 "{%0,%1,%2,%3}, {%4,%5,%6,%7}, {%8,%9}, {%0,%1,%2,%3};"
                 : "+f"(c[0]), "+f"(c[1]), "+f"(c[2]), "+f"(c[3])
                 : "r"(a[0]), "r"(a[1]), "r"(a[2]), "r"(a[3]), "r"(b[0]), "r"(b[1]));
}
__device__ __forceinline__ void cp16(uint32_t dst, const void* src) {
    asm volatile("cp.async.cg.shared.global [%0], [%1], 16;" :: "r"(dst), "l"(src));
}
#define CP_COMMIT() asm volatile("cp.async.commit_group;" ::: "memory")
#define CP_WAIT0()  asm volatile("cp.async.wait_group 0;" ::: "memory")
#define CP_WAIT1()  asm volatile("cp.async.wait_group 1;" ::: "memory")

// ---------------- weight prep: W[K,256] fp32 -> Bt[256,K] tf32-rounded fp32 ----
__global__ void k_prep_Bt(const float* __restrict__ W, float* __restrict__ Bt, int K) {
    __shared__ float tile[32][33];
    int t = threadIdx.x;
    int k0 = blockIdx.x * 32, n0 = blockIdx.y * 32;
#pragma unroll
    for (int p = 0; p < 4; p++) {
        int idx = t + 256 * p, i = idx >> 5, j = idx & 31;
        tile[i][j] = W[(size_t)(k0 + i) * HID + n0 + j];
    }
    __syncthreads();
    int jp = t >> 3, i0 = (t & 7) * 4;
    float o[4];
#pragma unroll
    for (int q = 0; q < 4; q++)
        o[q] = __uint_as_float(to_tf32(__float_as_uint(tile[i0 + q][jp])));
    *(float4*)&Bt[(size_t)(n0 + jp) * K + k0 + i0] = *(float4*)o;
}

// ---------------- TF32 GEMM: C[M,256] = A[M,K] @ W, CTA 128x128, 3-stage cp.async ----
// Stage: A 128 rows x 144B | B 128 rows x 144B  => 36864B; 3 stages.
#define ROWB   144
#define SM_B   18432
#define SSTAGE 36864
#define TG_SMEM (3 * SSTAGE)

__global__ __launch_bounds__(256, 2)
void k_tgemm(const float* __restrict__ A, const float* __restrict__ Bt,
             float* __restrict__ C, int K) {
    extern __shared__ char smem[];
    const uint32_t sb = smem_u32(smem);
    const int t = threadIdx.x;
    const int lane = t & 31, w = t >> 5;
    const int wm = w & 3, wn = w >> 2;              // 4M x 2N warps, warp tile 32x64
    const int mo = blockIdx.x * 128;
    const int nb = blockIdx.y * 128;
    const int nc = K / 32;

    const int lrow = t >> 1, lhalf = t & 1;         // loader: 2 threads/row, 64B each

    auto issue = [&](int c, int s) {
        uint32_t ad = sb + s * SSTAGE + lrow * ROWB + lhalf * 64;
        const float* As = A + (size_t)(mo + lrow) * K + c * 32 + lhalf * 16;
        const float* Bs = Bt + (size_t)(nb + lrow) * K + c * 32 + lhalf * 16;
#pragma unroll
        for (int q = 0; q < 4; q++) {
            cp16(ad + 16 * q, As + 4 * q);
            cp16(ad + SM_B + 16 * q, Bs + 4 * q);
        }
    };

    float acc[2][8][4];
#pragma unroll
    for (int i = 0; i < 2; i++)
#pragma unroll
        for (int j = 0; j < 8; j++)
#pragma unroll
            for (int e = 0; e < 4; e++) acc[i][j][e] = 0.f;

    // ldmatrix lane offsets (tf32 fragments via b16 ldmatrix word mapping)
    const uint32_t a_lane = (uint32_t)(((lane >> 3) & 1) * 8 + (lane & 7)) * ROWB + (uint32_t)(lane >> 4) * 16;
    const uint32_t b_lane = (uint32_t)(((lane >> 4) * 8) + (lane & 7)) * ROWB + (uint32_t)((lane >> 3) & 1) * 16;

    // prologue: stages 0,1
    issue(0, 0); CP_COMMIT();
    if (nc > 1) { issue(1, 1); CP_COMMIT(); }

    for (int c = 0; c < nc; c++) {
        if (c + 1 < nc) { CP_WAIT1(); } else { CP_WAIT0(); }
        __syncthreads();
        if (c + 2 < nc) { issue(c + 2, (c + 2) % 3); CP_COMMIT(); }

        const uint32_t stage = sb + (c % 3) * SSTAGE;
#pragma unroll
        for (int kk = 0; kk < 4; kk++) {
            const uint32_t KB = (uint32_t)kk * 32;
            uint32_t a[2][4];
#pragma unroll
            for (int mt = 0; mt < 2; mt++) {
                uint32_t raw[4];
                ldm_x4(stage + (uint32_t)(wm * 32 + mt * 16) * ROWB + KB + a_lane, raw);
#pragma unroll
                for (int i = 0; i < 4; i++) a[mt][i] = to_tf32(raw[i]);
            }
            uint32_t b[8][2];
#pragma unroll
            for (int pr = 0; pr < 4; pr++) {
                uint32_t r[4];
                ldm_x4(stage + SM_B + (uint32_t)(wn * 64 + pr * 16) * ROWB + KB + b_lane, r);
                b[2 * pr][0] = r[0]; b[2 * pr][1] = r[1];
                b[2 * pr + 1][0] = r[2]; b[2 * pr + 1][1] = r[3];
            }
#pragma unroll
            for (int mt = 0; mt < 2; mt++)
#pragma unroll
                for (int nt = 0; nt < 8; nt++) mma_tf32(acc[mt][nt], a[mt], b[nt]);
        }
    }

    // epilogue
#pragma unroll
    for (int mt = 0; mt < 2; mt++) {
        int r0 = mo + wm * 32 + mt * 16 + (lane >> 2);
#pragma unroll
        for (int nt = 0; nt < 8; nt++) {
            int cb = nb + wn * 64 + nt * 8 + (lane & 3) * 2;
            float2 v0 = make_float2(acc[mt][nt][0], acc[mt][nt][1]);
            float2 v1 = make_float2(acc[mt][nt][2], acc[mt][nt][3]);
            *(float2*)(C + (size_t)r0 * HID + cb)       = v0;
            *(float2*)(C + (size_t)(r0 + 8) * HID + cb) = v1;
        }
    }
}

// ---------------- degree / CSR construction ----------------
__global__ void k_init_deg() {
    int i = blockIdx.x * blockDim.x + threadIdx.x;
    if (i < NN) g_deg[i] = 1;
}
__global__ void k_count_deg(const int* __restrict__ dst, int E) {
    int i = blockIdx.x * blockDim.x + threadIdx.x;
    if (i < E) atomicAdd(&g_deg[dst[i]], 1);
}
__global__ void k_dinv() {
    int i = blockIdx.x * blockDim.x + threadIdx.x;
    if (i < NN) g_dinv[i] = rsqrtf((float)g_deg[i]);
}
__global__ void k_scan() {
    __shared__ int sh[1024];
    int tid = threadIdx.x;
    int local[16];
    int sum = 0;
#pragma unroll
    for (int i = 0; i < 16; i++) { local[i] = g_deg[tid * 16 + i]; sum += local[i]; }
    sh[tid] = sum;
    __syncthreads();
    for (int off = 1; off < 1024; off <<= 1) {
        int v = (tid >= off) ? sh[tid - off] : 0;
        __syncthreads();
        sh[tid] += v;
        __syncthreads();
    }
    int run = (tid == 0) ? 0 : sh[tid - 1];
#pragma unroll
    for (int i = 0; i < 16; i++) {
        g_rowstart[tid * 16 + i] = run;
        g_cursor[tid * 16 + i]   = run;
        run += local[i];
    }
    if (tid == 1023) g_rowstart[NN] = run;
}
__global__ void k_fill(const int* __restrict__ src, const int* __restrict__ dst, int E) {
    int i = blockIdx.x * blockDim.x + threadIdx.x;
    if (i >= E + NN) return;
    int s, d;
    if (i < E) { s = src[i]; d = dst[i]; }
    else       { s = i - E; d = s; }
    int slot = atomicAdd(&g_cursor[d], 1);
    g_csr[slot] = s;
}
__global__ void k_sort_rows() {
    __shared__ int s[1024];
    int r = blockIdx.x;
    int beg = g_rowstart[r], end = g_rowstart[r + 1];
    int len = end - beg;
    if (len <= 1 || len > 1024) return;
    for (int i = threadIdx.x; i < len; i += blockDim.x) s[i] = g_csr[beg + i];
    __syncthreads();
    for (int ph = 0; ph < len; ph++) {
        int off = ph & 1;
        for (int j = off + 2 * (int)threadIdx.x; j + 1 < len; j += 2 * (int)blockDim.x) {
            int a = s[j], b = s[j + 1];
            if (a > b) { s[j] = b; s[j + 1] = a; }
        }
        __syncthreads();
    }
    for (int i = threadIdx.x; i < len; i += blockDim.x) g_csr[beg + i] = s[i];
}

// ---------------- aggregation ----------------
__global__ void k_agg(const float* __restrict__ hin, float* __restrict__ hout,
                      const float* __restrict__ bias) {
    int v = blockIdx.x;
    int t = threadIdx.x;
    int beg = g_rowstart[v], end = g_rowstart[v + 1];
    float dv = g_dinv[v];
    __shared__ int   ssrc[256];
    __shared__ float snorm[256];
    float acc = 0.f;
    for (int base = beg; base < end; base += 256) {
        int n = min(256, end - base);
        if (t < n) {
            int s = g_csr[base + t];
            ssrc[t]  = s * HID;
            snorm[t] = g_dinv[s] * dv;
        }
        __syncthreads();
        int j = 0;
        for (; j + 4 <= n; j += 4) {
            float x0 = hin[ssrc[j]     + t];
            float x1 = hin[ssrc[j + 1] + t];
            float x2 = hin[ssrc[j + 2] + t];
            float x3 = hin[ssrc[j + 3] + t];
            acc += x0 * snorm[j] + x1 * snorm[j + 1] + x2 * snorm[j + 2] + x3 * snorm[j + 3];
        }
        for (; j < n; j++) acc += hin[ssrc[j] + t] * snorm[j];
        __syncthreads();
    }
    float r = acc + bias[t];
    hout[(size_t)v * HID + t] = r > 0.f ? r : 0.f;
}

// ---------------- edge scoring ----------------
__global__ void k_scores(const float* __restrict__ linW) {
    int v = blockIdx.x, t = threadIdx.x;
    float hv = g_h2[(size_t)v * HID + t];
    __shared__ float sa[256], sb2[256];
    sa[t]  = hv * linW[t];
    sb2[t] = hv * linW[HID + t];
    __syncthreads();
    for (int s = 128; s > 0; s >>= 1) {
        if (t < s) { sa[t] += sa[t + s]; sb2[t] += sb2[t + s]; }
        __syncthreads();
    }
    if (t == 0) { g_sa[v] = sa[0]; g_sb[v] = sb2[0]; }
}
__global__ void k_edge_out(const int* __restrict__ src, const int* __restrict__ dst,
                           const float* __restrict__ linb, float* __restrict__ out, int E) {
    int i = blockIdx.x * blockDim.x + threadIdx.x;
    if (i < E) out[i] = g_sa[src[i]] + g_sb[dst[i]] + linb[0];
}

// ---------------- launch ----------------
extern "C" void kernel_launch(void* const* d_in, const int* in_sizes, int n_in,
                              void* d_out, int out_size) {
    const float* x    = (const float*)d_in[0];
    const int*   ei   = (const int*)d_in[1];
    const float* W1   = (const float*)d_in[2];
    const float* b1   = (const float*)d_in[3];
    const float* W2   = (const float*)d_in[4];
    const float* b2   = (const float*)d_in[5];
    const float* linW = (const float*)d_in[6];
    const float* linb = (const float*)d_in[7];
    float* out = (float*)d_out;

    int E = in_sizes[1] / 2;
    const int* esrc = ei;
    const int* edst = ei + E;

    float *h1, *h2, *B1, *B2;
    cudaGetSymbolAddress((void**)&h1, g_h1);
    cudaGetSymbolAddress((void**)&h2, g_h2);
    cudaGetSymbolAddress((void**)&B1, g_B1f);
    cudaGetSymbolAddress((void**)&B2, g_B2f);

    cudaFuncSetAttribute(k_tgemm, cudaFuncAttributeMaxDynamicSharedMemorySize, TG_SMEM);

    // launch order arranged so k_tgemm (layer 1) is launch index 3 -> ncu captures it
    k_prep_Bt<<<dim3(NN / 32, HID / 32), 256>>>(W1, B1, NN);       // 0
    k_prep_Bt<<<dim3(HID / 32, HID / 32), 256>>>(W2, B2, HID);     // 1
    k_init_deg<<<NN / 256, 256>>>();                               // 2
    k_tgemm<<<dim3(NN / 128, 2), 256, TG_SMEM>>>(x, B1, h1, NN);   // 3 <- profile target

    // graph structure
    k_count_deg<<<(E + 255) / 256, 256>>>(edst, E);
    k_dinv<<<NN / 256, 256>>>();
    k_scan<<<1, 1024>>>();
    k_fill<<<(E + NN + 255) / 256, 256>>>(esrc, edst, E);
    k_sort_rows<<<NN, 256>>>();

    // layer 1 aggregation
    k_agg<<<NN, 256>>>(h1, h2, b1);
    // layer 2
    k_tgemm<<<dim3(NN / 128, 2), 256, TG_SMEM>>>(h2, B2, h1, HID);
    k_agg<<<NN, 256>>>(h1, h2, b2);

    // edge scores
    k_scores<<<NN, 256>>>(linW);
    k_edge_out<<<(E + 255) / 256, 256>>>(esrc, edst, linb, out, E);
}

// round 9
// speedup vs baseline: 1.1328x; 1.0170x over previous
#include <cuda_runtime.h>
#include <cstdint>

#define NN   16384
#define HID  256
#define NEMAX 1048576
#define ETOT (NEMAX + NN)

// ---------------- device scratch ----------------
__device__ float g_h1[(size_t)NN * HID];
__device__ float g_h2[(size_t)NN * HID];
__device__ int   g_deg[NN];
__device__ float g_dinv[NN];
__device__ int   g_rowstart[NN + 1];
__device__ int   g_cursor[NN];
__device__ int   g_csr[ETOT];
__device__ float g_sa[NN];
__device__ float g_sb[NN];
// tf32-rounded transposed weights, [N=256, K] row-major
__device__ float g_B1f[(size_t)HID * NN];
__device__ float g_B2f[(size_t)HID * HID];

__device__ __forceinline__ uint32_t smem_u32(const void* p) {
    uint32_t a;
    asm("{ .reg .u64 t; cvta.to.shared.u64 t, %1; cvt.u32.u64 %0, t; }" : "=r"(a) : "l"(p));
    return a;
}
__device__ __forceinline__ void ldm_x4(uint32_t addr, uint32_t* r) {
    asm volatile("ldmatrix.sync.aligned.m8n8.x4.shared.b16 {%0,%1,%2,%3}, [%4];"
                 : "=r"(r[0]), "=r"(r[1]), "=r"(r[2]), "=r"(r[3]) : "r"(addr));
}
__device__ __forceinline__ uint32_t to_tf32(uint32_t raw) {
    uint32_t o;
    asm("cvt.rna.tf32.f32 %0, %1;" : "=r"(o) : "f"(__uint_as_float(raw)));
    return o;
}
__device__ __forceinline__ void mma_tf32(float* c, const uint32_t* a, const uint32_t* b) {
    asm volatile("mma.sync.aligned.m16n8k8.row.col.f32.tf32.tf32.f32 "
                 "{%0,%1,%2,%3}, {%4,%5,%6,%7}, {%8,%9}, {%0,%1,%2,%3};"
                 : "+f"(c[0]), "+f"(c[1]), "+f"(c[2]), "+f"(c[3])
                 : "r"(a[0]), "r"(a[1]), "r"(a[2]), "r"(a[3]), "r"(b[0]), "r"(b[1]));
}
__device__ __forceinline__ void cp16(uint32_t dst, const void* src) {
    asm volatile("cp.async.cg.shared.global [%0], [%1], 16;" :: "r"(dst), "l"(src));
}
#define CP_COMMIT() asm volatile("cp.async.commit_group;" ::: "memory")
#define CP_WAIT0()  asm volatile("cp.async.wait_group 0;" ::: "memory")
#define CP_WAIT1()  asm volatile("cp.async.wait_group 1;" ::: "memory")

// ---------------- weight prep: W[K,256] fp32 -> Bt[256,K] tf32-rounded fp32 ----
__global__ void k_prep_Bt(const float* __restrict__ W, float* __restrict__ Bt, int K) {
    __shared__ float tile[32][33];
    int t = threadIdx.x;
    int k0 = blockIdx.x * 32, n0 = blockIdx.y * 32;
#pragma unroll
    for (int p = 0; p < 4; p++) {
        int idx = t + 256 * p, i = idx >> 5, j = idx & 31;
        tile[i][j] = W[(size_t)(k0 + i) * HID + n0 + j];
    }
    __syncthreads();
    int jp = t >> 3, i0 = (t & 7) * 4;
    float o[4];
#pragma unroll
    for (int q = 0; q < 4; q++)
        o[q] = __uint_as_float(to_tf32(__float_as_uint(tile[i0 + q][jp])));
    *(float4*)&Bt[(size_t)(n0 + jp) * K + k0 + i0] = *(float4*)o;
}

// ---------------- TF32 GEMM: C[M,256] = A[M,K] @ W, CTA 128x128, 3-stage cp.async ----
// Stage: A 128 rows x 144B | B 128 rows x 144B  => 36864B; 3 stages.
#define ROWB   144
#define SM_B   18432
#define SSTAGE 36864
#define TG_SMEM (3 * SSTAGE)

__global__ __launch_bounds__(256, 2)
void k_tgemm(const float* __restrict__ A, const float* __restrict__ Bt,
             float* __restrict__ C, int K) {
    extern __shared__ char smem[];
    const uint32_t sb = smem_u32(smem);
    const int t = threadIdx.x;
    const int lane = t & 31, w = t >> 5;
    const int wm = w & 3, wn = w >> 2;              // 4M x 2N warps, warp tile 32x64
    const int mo = blockIdx.x * 128;
    const int nb = blockIdx.y * 128;
    const int nc = K / 32;

    const int lrow = t >> 1, lhalf = t & 1;         // loader: 2 threads/row, 64B each

    auto issue = [&](int c, int s) {
        uint32_t ad = sb + s * SSTAGE + lrow * ROWB + lhalf * 64;
        const float* As = A + (size_t)(mo + lrow) * K + c * 32 + lhalf * 16;
        const float* Bs = Bt + (size_t)(nb + lrow) * K + c * 32 + lhalf * 16;
#pragma unroll
        for (int q = 0; q < 4; q++) {
            cp16(ad + 16 * q, As + 4 * q);
            cp16(ad + SM_B + 16 * q, Bs + 4 * q);
        }
    };

    float acc[2][8][4];
#pragma unroll
    for (int i = 0; i < 2; i++)
#pragma unroll
        for (int j = 0; j < 8; j++)
#pragma unroll
            for (int e = 0; e < 4; e++) acc[i][j][e] = 0.f;

    // ldmatrix lane offsets (tf32 fragments via b16 ldmatrix word mapping)
    const uint32_t a_lane = (uint32_t)(((lane >> 3) & 1) * 8 + (lane & 7)) * ROWB + (uint32_t)(lane >> 4) * 16;
    const uint32_t b_lane = (uint32_t)(((lane >> 4) * 8) + (lane & 7)) * ROWB + (uint32_t)((lane >> 3) & 1) * 16;

    // double-buffered fragments (explicit software pipeline across kk)
    uint32_t abuf[2][2][4];
    uint32_t bbuf[2][8][2];

    auto ldfrag = [&](uint32_t stage, int kk, int pb) {
        const uint32_t KB = (uint32_t)kk * 32;
#pragma unroll
        for (int mt = 0; mt < 2; mt++) {
            uint32_t raw[4];
            ldm_x4(stage + (uint32_t)(wm * 32 + mt * 16) * ROWB + KB + a_lane, raw);
#pragma unroll
            for (int i = 0; i < 4; i++) abuf[pb][mt][i] = to_tf32(raw[i]);
        }
#pragma unroll
        for (int pr = 0; pr < 4; pr++) {
            uint32_t r[4];
            ldm_x4(stage + SM_B + (uint32_t)(wn * 64 + pr * 16) * ROWB + KB + b_lane, r);
            bbuf[pb][2 * pr][0] = r[0]; bbuf[pb][2 * pr][1] = r[1];
            bbuf[pb][2 * pr + 1][0] = r[2]; bbuf[pb][2 * pr + 1][1] = r[3];
        }
    };
    auto do_mma = [&](int pb) {
#pragma unroll
        for (int mt = 0; mt < 2; mt++)
#pragma unroll
            for (int nt = 0; nt < 8; nt++) mma_tf32(acc[mt][nt], abuf[pb][mt], bbuf[pb][nt]);
    };

    // prologue: stages 0,1
    issue(0, 0); CP_COMMIT();
    if (nc > 1) { issue(1, 1); CP_COMMIT(); }

    for (int c = 0; c < nc; c++) {
        if (c + 1 < nc) { CP_WAIT1(); } else { CP_WAIT0(); }
        __syncthreads();

        const uint32_t stage = sb + (c % 3) * SSTAGE;
        ldfrag(stage, 0, 0);                      // first frags of this chunk
        if (c + 2 < nc) { issue(c + 2, (c + 2) % 3); CP_COMMIT(); }

#pragma unroll
        for (int kk = 0; kk < 4; kk++) {
            if (kk < 3) ldfrag(stage, kk + 1, (kk + 1) & 1);  // prefetch next frags
            do_mma(kk & 1);                                   // overlap MMA with LDSM
        }
    }

    // epilogue
#pragma unroll
    for (int mt = 0; mt < 2; mt++) {
        int r0 = mo + wm * 32 + mt * 16 + (lane >> 2);
#pragma unroll
        for (int nt = 0; nt < 8; nt++) {
            int cb = nb + wn * 64 + nt * 8 + (lane & 3) * 2;
            float2 v0 = make_float2(acc[mt][nt][0], acc[mt][nt][1]);
            float2 v1 = make_float2(acc[mt][nt][2], acc[mt][nt][3]);
            *(float2*)(C + (size_t)r0 * HID + cb)       = v0;
            *(float2*)(C + (size_t)(r0 + 8) * HID + cb) = v1;
        }
    }
}

// ---------------- degree / CSR construction ----------------
__global__ void k_init_deg() {
    int i = blockIdx.x * blockDim.x + threadIdx.x;
    if (i < NN) g_deg[i] = 1;
}
__global__ void k_count_deg(const int* __restrict__ dst, int E) {
    int i = blockIdx.x * blockDim.x + threadIdx.x;
    if (i < E) atomicAdd(&g_deg[dst[i]], 1);
}
__global__ void k_dinv() {
    int i = blockIdx.x * blockDim.x + threadIdx.x;
    if (i < NN) g_dinv[i] = rsqrtf((float)g_deg[i]);
}
__global__ void k_scan() {
    __shared__ int sh[1024];
    int tid = threadIdx.x;
    int local[16];
    int sum = 0;
#pragma unroll
    for (int i = 0; i < 16; i++) { local[i] = g_deg[tid * 16 + i]; sum += local[i]; }
    sh[tid] = sum;
    __syncthreads();
    for (int off = 1; off < 1024; off <<= 1) {
        int v = (tid >= off) ? sh[tid - off] : 0;
        __syncthreads();
        sh[tid] += v;
        __syncthreads();
    }
    int run = (tid == 0) ? 0 : sh[tid - 1];
#pragma unroll
    for (int i = 0; i < 16; i++) {
        g_rowstart[tid * 16 + i] = run;
        g_cursor[tid * 16 + i]   = run;
        run += local[i];
    }
    if (tid == 1023) g_rowstart[NN] = run;
}
__global__ void k_fill(const int* __restrict__ src, const int* __restrict__ dst, int E) {
    int i = blockIdx.x * blockDim.x + threadIdx.x;
    if (i >= E + NN) return;
    int s, d;
    if (i < E) { s = src[i]; d = dst[i]; }
    else       { s = i - E; d = s; }
    int slot = atomicAdd(&g_cursor[d], 1);
    g_csr[slot] = s;
}
__global__ void k_sort_rows() {
    __shared__ int s[1024];
    int r = blockIdx.x;
    int beg = g_rowstart[r], end = g_rowstart[r + 1];
    int len = end - beg;
    if (len <= 1 || len > 1024) return;
    for (int i = threadIdx.x; i < len; i += blockDim.x) s[i] = g_csr[beg + i];
    __syncthreads();
    for (int ph = 0; ph < len; ph++) {
        int off = ph & 1;
        for (int j = off + 2 * (int)threadIdx.x; j + 1 < len; j += 2 * (int)blockDim.x) {
            int a = s[j], b = s[j + 1];
            if (a > b) { s[j] = b; s[j + 1] = a; }
        }
        __syncthreads();
    }
    for (int i = threadIdx.x; i < len; i += blockDim.x) g_csr[beg + i] = s[i];
}

// ---------------- aggregation ----------------
__global__ void k_agg(const float* __restrict__ hin, float* __restrict__ hout,
                      const float* __restrict__ bias) {
    int v = blockIdx.x;
    int t = threadIdx.x;
    int beg = g_rowstart[v], end = g_rowstart[v + 1];
    float dv = g_dinv[v];
    __shared__ int   ssrc[256];
    __shared__ float snorm[256];
    float acc = 0.f;
    for (int base = beg; base < end; base += 256) {
        int n = min(256, end - base);
        if (t < n) {
            int s = g_csr[base + t];
            ssrc[t]  = s * HID;
            snorm[t] = g_dinv[s] * dv;
        }
        __syncthreads();
        int j = 0;
        for (; j + 4 <= n; j += 4) {
            float x0 = hin[ssrc[j]     + t];
            float x1 = hin[ssrc[j + 1] + t];
            float x2 = hin[ssrc[j + 2] + t];
            float x3 = hin[ssrc[j + 3] + t];
            acc += x0 * snorm[j] + x1 * snorm[j + 1] + x2 * snorm[j + 2] + x3 * snorm[j + 3];
        }
        for (; j < n; j++) acc += hin[ssrc[j] + t] * snorm[j];
        __syncthreads();
    }
    float r = acc + bias[t];
    hout[(size_t)v * HID + t] = r > 0.f ? r : 0.f;
}

// ---------------- edge scoring ----------------
__global__ void k_scores(const float* __restrict__ linW) {
    int v = blockIdx.x, t = threadIdx.x;
    float hv = g_h2[(size_t)v * HID + t];
    __shared__ float sa[256], sb2[256];
    sa[t]  = hv * linW[t];
    sb2[t] = hv * linW[HID + t];
    __syncthreads();
    for (int s = 128; s > 0; s >>= 1) {
        if (t < s) { sa[t] += sa[t + s]; sb2[t] += sb2[t + s]; }
        __syncthreads();
    }
    if (t == 0) { g_sa[v] = sa[0]; g_sb[v] = sb2[0]; }
}
__global__ void k_edge_out(const int* __restrict__ src, const int* __restrict__ dst,
                           const float* __restrict__ linb, float* __restrict__ out, int E) {
    int i = blockIdx.x * blockDim.x + threadIdx.x;
    if (i < E) out[i] = g_sa[src[i]] + g_sb[dst[i]] + linb[0];
}

// ---------------- launch ----------------
extern "C" void kernel_launch(void* const* d_in, const int* in_sizes, int n_in,
                              void* d_out, int out_size) {
    const float* x    = (const float*)d_in[0];
    const int*   ei   = (const int*)d_in[1];
    const float* W1   = (const float*)d_in[2];
    const float* b1   = (const float*)d_in[3];
    const float* W2   = (const float*)d_in[4];
    const float* b2   = (const float*)d_in[5];
    const float* linW = (const float*)d_in[6];
    const float* linb = (const float*)d_in[7];
    float* out = (float*)d_out;

    int E = in_sizes[1] / 2;
    const int* esrc = ei;
    const int* edst = ei + E;

    float *h1, *h2, *B1, *B2;
    cudaGetSymbolAddress((void**)&h1, g_h1);
    cudaGetSymbolAddress((void**)&h2, g_h2);
    cudaGetSymbolAddress((void**)&B1, g_B1f);
    cudaGetSymbolAddress((void**)&B2, g_B2f);

    cudaFuncSetAttribute(k_tgemm, cudaFuncAttributeMaxDynamicSharedMemorySize, TG_SMEM);

    // launch order arranged so k_tgemm (layer 1) is launch index 3 -> ncu captures it
    k_prep_Bt<<<dim3(NN / 32, HID / 32), 256>>>(W1, B1, NN);       // 0
    k_prep_Bt<<<dim3(HID / 32, HID / 32), 256>>>(W2, B2, HID);     // 1
    k_init_deg<<<NN / 256, 256>>>();                               // 2
    k_tgemm<<<dim3(NN / 128, 2), 256, TG_SMEM>>>(x, B1, h1, NN);   // 3 <- profile target

    // graph structure
    k_count_deg<<<(E + 255) / 256, 256>>>(edst, E);
    k_dinv<<<NN / 256, 256>>>();
    k_scan<<<1, 1024>>>();
    k_fill<<<(E + NN + 255) / 256, 256>>>(esrc, edst, E);
    k_sort_rows<<<NN, 256>>>();

    // layer 1 aggregation
    k_agg<<<NN, 256>>>(h1, h2, b1);
    // layer 2
    k_tgemm<<<dim3(NN / 128, 2), 256, TG_SMEM>>>(h2, B2, h1, HID);
    k_agg<<<NN, 256>>>(h1, h2, b2);

    // edge scores
    k_scores<<<NN, 256>>>(linW);
    k_edge_out<<<(E + 255) / 256, 256>>>(esrc, edst, linb, out, E);
}

// round 10
// speedup vs baseline: 1.7345x; 1.5312x over previous
#include <cuda_runtime.h>
#include <cuda_bf16.h>
#include <cstdint>

#define NN   16384
#define HID  256
#define NEMAX 1048576
#define ETOT (NEMAX + NN)

// ---------------- device scratch ----------------
__device__ float g_h1[(size_t)NN * HID];
__device__ float g_h2[(size_t)NN * HID];
__device__ int   g_deg[NN];
__device__ float g_dinv[NN];
__device__ int   g_rowstart[NN + 1];
__device__ int   g_cursor[NN];
__device__ int   g_csr[ETOT];
__device__ float g_sa[NN];
__device__ float g_sb[NN];
// bf16 transposed weights [N=256, K] row-major (single precision level, no split)
__device__ __nv_bfloat16 g_B1[(size_t)HID * NN];
__device__ __nv_bfloat16 g_B2[(size_t)HID * HID];

__device__ __forceinline__ uint32_t smem_u32(const void* p) {
    uint32_t a;
    asm("{ .reg .u64 t; cvta.to.shared.u64 t, %1; cvt.u32.u64 %0, t; }" : "=r"(a) : "l"(p));
    return a;
}
__device__ __forceinline__ void ldm_x4(uint32_t addr, uint32_t* r) {
    asm volatile("ldmatrix.sync.aligned.m8n8.x4.shared.b16 {%0,%1,%2,%3}, [%4];"
                 : "=r"(r[0]), "=r"(r[1]), "=r"(r[2]), "=r"(r[3]) : "r"(addr));
}
__device__ __forceinline__ void mma_bf16(float* c, const uint32_t* a, const uint32_t* b) {
    asm volatile("mma.sync.aligned.m16n8k16.row.col.f32.bf16.bf16.f32 "
                 "{%0,%1,%2,%3}, {%4,%5,%6,%7}, {%8,%9}, {%0,%1,%2,%3};"
                 : "+f"(c[0]), "+f"(c[1]), "+f"(c[2]), "+f"(c[3])
                 : "r"(a[0]), "r"(a[1]), "r"(a[2]), "r"(a[3]), "r"(b[0]), "r"(b[1]));
}
__device__ __forceinline__ void cp16(uint32_t dst, const void* src) {
    asm volatile("cp.async.cg.shared.global [%0], [%1], 16;" :: "r"(dst), "l"(src));
}
#define CP_COMMIT() asm volatile("cp.async.commit_group;" ::: "memory")
#define CP_WAIT0()  asm volatile("cp.async.wait_group 0;" ::: "memory")

// ---------------- weight prep: W[K,256] fp32 -> gB[256,K] bf16 transposed ----
__global__ void k_prep_B(const float* __restrict__ W, __nv_bfloat16* __restrict__ gB, int K) {
    __shared__ float tile[32][33];
    int t = threadIdx.x;
    int k0 = blockIdx.x * 32, n0 = blockIdx.y * 32;
#pragma unroll
    for (int p = 0; p < 4; p++) {
        int idx = t + 256 * p, i = idx >> 5, j = idx & 31;
        tile[i][j] = W[(size_t)(k0 + i) * HID + n0 + j];
    }
    __syncthreads();
    int jp = t >> 3, i0 = (t & 7) * 4;
    __nv_bfloat16 o[4];
#pragma unroll
    for (int q = 0; q < 4; q++) o[q] = __float2bfloat16(tile[i0 + q][jp]);
    *(uint2*)&gB[(size_t)(n0 + jp) * K + k0 + i0] = *(uint2*)o;
}

// ---------------- single-pass bf16 GEMM: C[M,256] = A[M,K] @ W ----
// CTA 128x128, 8 warps (4M x 2N), warp 32x64, BK=32, double buffered, 2 CTAs/SM.
// Stage: A 128x80B (10240) | B 128x80B (10240) = 20480B; x2 stages = 40960B.
#define TILE_BYTES 10240
#define STAGE_BYTES 20480
#define HG_SMEM (2 * STAGE_BYTES)

__global__ __launch_bounds__(256, 2)
void k_hgemm(const float* __restrict__ A, const __nv_bfloat16* __restrict__ gB,
             float* __restrict__ C, int K) {
    extern __shared__ char smem[];
    const uint32_t sb = smem_u32(smem);
    const int t = threadIdx.x;
    const int lane = t & 31, w = t >> 5;
    const int wm = w & 3, wn = w >> 2;
    const int mo = blockIdx.x * 128;
    const int nb = blockIdx.y * 128;
    const int nc = K / 32;

    const int arow = t >> 1, acol = (t & 1) * 16;   // A: 128 rows x 32 cols fp32
    const int brow = t >> 1, bpart = t & 1;         // B: 128 rows x 32 cols bf16

    float4 xa[4];

    auto ldgA = [&](int c) {
        const float* Ap = A + (size_t)(mo + arow) * K + c * 32 + acol;
        xa[0] = *(const float4*)(Ap + 0);
        xa[1] = *(const float4*)(Ap + 4);
        xa[2] = *(const float4*)(Ap + 8);
        xa[3] = *(const float4*)(Ap + 12);
    };
    auto cpB = [&](int c, int st) {
        uint32_t dst = sb + st * STAGE_BYTES + TILE_BYTES + brow * 80 + bpart * 32;
        const __nv_bfloat16* Bp = gB + (size_t)(nb + brow) * K + c * 32 + bpart * 16;
        cp16(dst, Bp);
        cp16(dst + 16, Bp + 8);
    };
    auto stsA = [&](int st) {
        char* base = smem + st * STAGE_BYTES;
        __nv_bfloat16 h[16];
#pragma unroll
        for (int q = 0; q < 4; q++) {
            h[q * 4 + 0] = __float2bfloat16(xa[q].x);
            h[q * 4 + 1] = __float2bfloat16(xa[q].y);
            h[q * 4 + 2] = __float2bfloat16(xa[q].z);
            h[q * 4 + 3] = __float2bfloat16(xa[q].w);
        }
        uint32_t aoff = arow * 80 + acol * 2;
        *(uint4*)(base + aoff)      = *(uint4*)&h[0];
        *(uint4*)(base + aoff + 16) = *(uint4*)&h[8];
    };

    float acc[2][8][4];
#pragma unroll
    for (int i = 0; i < 2; i++)
#pragma unroll
        for (int j = 0; j < 8; j++)
#pragma unroll
            for (int e = 0; e < 4; e++) acc[i][j][e] = 0.f;

    const int lm = lane & 7, sel = lane >> 3;
    const uint32_t a_row_off = (uint32_t)(wm * 32 + (sel & 1) * 8 + lm) * 80 + (uint32_t)(sel >> 1) * 16;
    const uint32_t b_row_off = (uint32_t)(wn * 64 + (sel >> 1) * 8 + lm) * 80 + (uint32_t)(sel & 1) * 16;

    // prologue
    cpB(0, 0);
    CP_COMMIT();
    ldgA(0);
    stsA(0);
    CP_WAIT0();
    __syncthreads();

    for (int c = 0; c < nc; c++) {
        const int st = c & 1;
        if (c + 1 < nc) {
            cpB(c + 1, st ^ 1);
            CP_COMMIT();
            ldgA(c + 1);
        }

        const uint32_t stage = sb + st * STAGE_BYTES;
#pragma unroll
        for (int kk = 0; kk < 2; kk++) {
            const uint32_t kb = (uint32_t)kk * 32;
            uint32_t a[2][4];
#pragma unroll
            for (int mt = 0; mt < 2; mt++)
                ldm_x4(stage + a_row_off + (uint32_t)mt * (16 * 80) + kb, a[mt]);
            uint32_t b[8][2];
#pragma unroll
            for (int pr = 0; pr < 4; pr++) {
                uint32_t r[4];
                ldm_x4(stage + TILE_BYTES + b_row_off + (uint32_t)pr * (16 * 80) + kb, r);
                b[2 * pr][0] = r[0]; b[2 * pr][1] = r[1];
                b[2 * pr + 1][0] = r[2]; b[2 * pr + 1][1] = r[3];
            }
#pragma unroll
            for (int mt = 0; mt < 2; mt++)
#pragma unroll
                for (int nt = 0; nt < 8; nt++) mma_bf16(acc[mt][nt], a[mt], b[nt]);
        }
        if (c + 1 < nc) stsA(st ^ 1);
        CP_WAIT0();
        __syncthreads();
    }

    // epilogue
#pragma unroll
    for (int mt = 0; mt < 2; mt++) {
        int r0 = mo + wm * 32 + mt * 16 + (lane >> 2);
#pragma unroll
        for (int nt = 0; nt < 8; nt++) {
            int cb = nb + wn * 64 + nt * 8 + (lane & 3) * 2;
            float2 v0 = make_float2(acc[mt][nt][0], acc[mt][nt][1]);
            float2 v1 = make_float2(acc[mt][nt][2], acc[mt][nt][3]);
            *(float2*)(C + (size_t)r0 * HID + cb)       = v0;
            *(float2*)(C + (size_t)(r0 + 8) * HID + cb) = v1;
        }
    }
}

// ---------------- degree / CSR construction ----------------
__global__ void k_init_deg() {
    int i = blockIdx.x * blockDim.x + threadIdx.x;
    if (i < NN) g_deg[i] = 1;
}
__global__ void k_count_deg(const int* __restrict__ dst, int E) {
    int i = blockIdx.x * blockDim.x + threadIdx.x;
    if (i < E) atomicAdd(&g_deg[dst[i]], 1);
}
__global__ void k_dinv() {
    int i = blockIdx.x * blockDim.x + threadIdx.x;
    if (i < NN) g_dinv[i] = rsqrtf((float)g_deg[i]);
}
__global__ void k_scan() {
    __shared__ int sh[1024];
    int tid = threadIdx.x;
    int local[16];
    int sum = 0;
#pragma unroll
    for (int i = 0; i < 16; i++) { local[i] = g_deg[tid * 16 + i]; sum += local[i]; }
    sh[tid] = sum;
    __syncthreads();
    for (int off = 1; off < 1024; off <<= 1) {
        int v = (tid >= off) ? sh[tid - off] : 0;
        __syncthreads();
        sh[tid] += v;
        __syncthreads();
    }
    int run = (tid == 0) ? 0 : sh[tid - 1];
#pragma unroll
    for (int i = 0; i < 16; i++) {
        g_rowstart[tid * 16 + i] = run;
        g_cursor[tid * 16 + i]   = run;
        run += local[i];
    }
    if (tid == 1023) g_rowstart[NN] = run;
}
__global__ void k_fill(const int* __restrict__ src, const int* __restrict__ dst, int E) {
    int i = blockIdx.x * blockDim.x + threadIdx.x;
    if (i >= E + NN) return;
    int s, d;
    if (i < E) { s = src[i]; d = dst[i]; }
    else       { s = i - E; d = s; }
    int slot = atomicAdd(&g_cursor[d], 1);
    g_csr[slot] = s;
}
__global__ void k_sort_rows() {
    __shared__ int s[1024];
    int r = blockIdx.x;
    int beg = g_rowstart[r], end = g_rowstart[r + 1];
    int len = end - beg;
    if (len <= 1 || len > 1024) return;
    for (int i = threadIdx.x; i < len; i += blockDim.x) s[i] = g_csr[beg + i];
    __syncthreads();
    for (int ph = 0; ph < len; ph++) {
        int off = ph & 1;
        for (int j = off + 2 * (int)threadIdx.x; j + 1 < len; j += 2 * (int)blockDim.x) {
            int a = s[j], b = s[j + 1];
            if (a > b) { s[j] = b; s[j + 1] = a; }
        }
        __syncthreads();
    }
    for (int i = threadIdx.x; i < len; i += blockDim.x) g_csr[beg + i] = s[i];
}

// ---------------- aggregation ----------------
__global__ void k_agg(const float* __restrict__ hin, float* __restrict__ hout,
                      const float* __restrict__ bias) {
    int v = blockIdx.x;
    int t = threadIdx.x;
    int beg = g_rowstart[v], end = g_rowstart[v + 1];
    float dv = g_dinv[v];
    __shared__ int   ssrc[256];
    __shared__ float snorm[256];
    float acc = 0.f;
    for (int base = beg; base < end; base += 256) {
        int n = min(256, end - base);
        if (t < n) {
            int s = g_csr[base + t];
            ssrc[t]  = s * HID;
            snorm[t] = g_dinv[s] * dv;
        }
        __syncthreads();
        int j = 0;
        for (; j + 4 <= n; j += 4) {
            float x0 = hin[ssrc[j]     + t];
            float x1 = hin[ssrc[j + 1] + t];
            float x2 = hin[ssrc[j + 2] + t];
            float x3 = hin[ssrc[j + 3] + t];
            acc += x0 * snorm[j] + x1 * snorm[j + 1] + x2 * snorm[j + 2] + x3 * snorm[j + 3];
        }
        for (; j < n; j++) acc += hin[ssrc[j] + t] * snorm[j];
        __syncthreads();
    }
    float r = acc + bias[t];
    hout[(size_t)v * HID + t] = r > 0.f ? r : 0.f;
}

// ---------------- edge scoring ----------------
__global__ void k_scores(const float* __restrict__ linW) {
    int v = blockIdx.x, t = threadIdx.x;
    float hv = g_h2[(size_t)v * HID + t];
    __shared__ float sa[256], sb2[256];
    sa[t]  = hv * linW[t];
    sb2[t] = hv * linW[HID + t];
    __syncthreads();
    for (int s = 128; s > 0; s >>= 1) {
        if (t < s) { sa[t] += sa[t + s]; sb2[t] += sb2[t + s]; }
        __syncthreads();
    }
    if (t == 0) { g_sa[v] = sa[0]; g_sb[v] = sb2[0]; }
}
__global__ void k_edge_out(const int* __restrict__ src, const int* __restrict__ dst,
                           const float* __restrict__ linb, float* __restrict__ out, int E) {
    int i = blockIdx.x * blockDim.x + threadIdx.x;
    if (i < E) out[i] = g_sa[src[i]] + g_sb[dst[i]] + linb[0];
}

// ---------------- launch ----------------
extern "C" void kernel_launch(void* const* d_in, const int* in_sizes, int n_in,
                              void* d_out, int out_size) {
    const float* x    = (const float*)d_in[0];
    const int*   ei   = (const int*)d_in[1];
    const float* W1   = (const float*)d_in[2];
    const float* b1   = (const float*)d_in[3];
    const float* W2   = (const float*)d_in[4];
    const float* b2   = (const float*)d_in[5];
    const float* linW = (const float*)d_in[6];
    const float* linb = (const float*)d_in[7];
    float* out = (float*)d_out;

    int E = in_sizes[1] / 2;
    const int* esrc = ei;
    const int* edst = ei + E;

    float *h1, *h2;
    __nv_bfloat16 *B1, *B2;
    cudaGetSymbolAddress((void**)&h1, g_h1);
    cudaGetSymbolAddress((void**)&h2, g_h2);
    cudaGetSymbolAddress((void**)&B1, g_B1);
    cudaGetSymbolAddress((void**)&B2, g_B2);

    cudaFuncSetAttribute(k_hgemm, cudaFuncAttributeMaxDynamicSharedMemorySize, HG_SMEM);

    // launch order arranged so k_hgemm (layer 1) is launch index 3 -> ncu captures it
    k_prep_B<<<dim3(NN / 32, HID / 32), 256>>>(W1, B1, NN);        // 0
    k_prep_B<<<dim3(HID / 32, HID / 32), 256>>>(W2, B2, HID);      // 1
    k_init_deg<<<NN / 256, 256>>>();                               // 2
    k_hgemm<<<dim3(NN / 128, 2), 256, HG_SMEM>>>(x, B1, h1, NN);   // 3 <- profile target

    // graph structure
    k_count_deg<<<(E + 255) / 256, 256>>>(edst, E);
    k_dinv<<<NN / 256, 256>>>();
    k_scan<<<1, 1024>>>();
    k_fill<<<(E + NN + 255) / 256, 256>>>(esrc, edst, E);
    k_sort_rows<<<NN, 256>>>();

    // layer 1 aggregation
    k_agg<<<NN, 256>>>(h1, h2, b1);
    // layer 2
    k_hgemm<<<dim3(NN / 128, 2), 256, HG_SMEM>>>(h2, B2, h1, HID);
    k_agg<<<NN, 256>>>(h1, h2, b2);

    // edge scores
    k_scores<<<NN, 256>>>(linW);
    k_edge_out<<<(E + 255) / 256, 256>>>(esrc, edst, linb, out, E);
}

// round 11
// speedup vs baseline: 1.7383x; 1.0022x over previous
#include <cuda_runtime.h>
#include <cuda_bf16.h>
#include <cstdint>

#define NN   16384
#define HID  256
#define NEMAX 1048576
#define ETOT (NEMAX + NN)

// ---------------- device scratch ----------------
__device__ float g_h1[(size_t)NN * HID];
__device__ float g_h2[(size_t)NN * HID];
__device__ int   g_deg[NN];
__device__ float g_dinv[NN];
__device__ int   g_rowstart[NN + 1];
__device__ int   g_cursor[NN];
__device__ int   g_csr[ETOT];
__device__ float g_sa[NN];
__device__ float g_sb[NN];
// bf16 transposed weights [N=256, K] row-major
__device__ __nv_bfloat16 g_B1[(size_t)HID * NN];
__device__ __nv_bfloat16 g_B2[(size_t)HID * HID];

__device__ __forceinline__ uint32_t smem_u32(const void* p) {
    uint32_t a;
    asm("{ .reg .u64 t; cvta.to.shared.u64 t, %1; cvt.u32.u64 %0, t; }" : "=r"(a) : "l"(p));
    return a;
}
__device__ __forceinline__ void ldm_x4(uint32_t addr, uint32_t* r) {
    asm volatile("ldmatrix.sync.aligned.m8n8.x4.shared.b16 {%0,%1,%2,%3}, [%4];"
                 : "=r"(r[0]), "=r"(r[1]), "=r"(r[2]), "=r"(r[3]) : "r"(addr));
}
__device__ __forceinline__ void mma_bf16(float* c, const uint32_t* a, const uint32_t* b) {
    asm volatile("mma.sync.aligned.m16n8k16.row.col.f32.bf16.bf16.f32 "
                 "{%0,%1,%2,%3}, {%4,%5,%6,%7}, {%8,%9}, {%0,%1,%2,%3};"
                 : "+f"(c[0]), "+f"(c[1]), "+f"(c[2]), "+f"(c[3])
                 : "r"(a[0]), "r"(a[1]), "r"(a[2]), "r"(a[3]), "r"(b[0]), "r"(b[1]));
}
__device__ __forceinline__ void cp16(uint32_t dst, const void* src) {
    asm volatile("cp.async.cg.shared.global [%0], [%1], 16;" :: "r"(dst), "l"(src));
}
#define CP_COMMIT() asm volatile("cp.async.commit_group;" ::: "memory")
#define CP_WAIT0()  asm volatile("cp.async.wait_group 0;" ::: "memory")

// ---------------- weight prep: W[K,256] fp32 -> gB[256,K] bf16 transposed ----
__global__ void k_prep_B(const float* __restrict__ W, __nv_bfloat16* __restrict__ gB, int K) {
    __shared__ float tile[32][33];
    int t = threadIdx.x;
    int k0 = blockIdx.x * 32, n0 = blockIdx.y * 32;
#pragma unroll
    for (int p = 0; p < 4; p++) {
        int idx = t + 256 * p, i = idx >> 5, j = idx & 31;
        tile[i][j] = W[(size_t)(k0 + i) * HID + n0 + j];
    }
    __syncthreads();
    int jp = t >> 3, i0 = (t & 7) * 4;
    __nv_bfloat16 o[4];
#pragma unroll
    for (int q = 0; q < 4; q++) o[q] = __float2bfloat16(tile[i0 + q][jp]);
    *(uint2*)&gB[(size_t)(n0 + jp) * K + k0 + i0] = *(uint2*)o;
}

// ---------------- single-pass bf16 GEMM: C[M,256] = A[M,K] @ W ----
// CTA 128x256 (full N), 8 warps (2M x 4N), warp tile 64x64, BK=32, 2-stage, 1 CTA/SM.
// Stage: A 128x80B (10240) | B 256x80B (20480) = 30720B; x2 = 61440B.
#define A_BYTES 10240
#define STAGE_BYTES 30720
#define HG_SMEM (2 * STAGE_BYTES)

__global__ __launch_bounds__(256, 1)
void k_hgemm(const float* __restrict__ A, const __nv_bfloat16* __restrict__ gB,
             float* __restrict__ C, int K) {
    extern __shared__ char smem[];
    const uint32_t sb = smem_u32(smem);
    const int t = threadIdx.x;
    const int lane = t & 31, w = t >> 5;
    const int wm = w & 1, wn = w >> 1;              // 2M x 4N warps, warp tile 64x64
    const int mo = blockIdx.x * 128;
    const int nc = K / 32;

    const int arow = t >> 1, acol = (t & 1) * 16;   // A: 128 rows x 32 fp32, 2 thr/row
    const int brow = t;                              // B: 256 rows x 32 bf16, 1 thr/row

    float4 xa[4];

    auto ldgA = [&](int c) {
        const float* Ap = A + (size_t)(mo + arow) * K + c * 32 + acol;
        xa[0] = *(const float4*)(Ap + 0);
        xa[1] = *(const float4*)(Ap + 4);
        xa[2] = *(const float4*)(Ap + 8);
        xa[3] = *(const float4*)(Ap + 12);
    };
    auto cpB = [&](int c, int st) {
        uint32_t dst = sb + st * STAGE_BYTES + A_BYTES + brow * 80;
        const __nv_bfloat16* Bp = gB + (size_t)brow * K + c * 32;
#pragma unroll
        for (int q = 0; q < 4; q++) cp16(dst + 16 * q, Bp + 8 * q);
    };
    auto stsA = [&](int st) {
        char* base = smem + st * STAGE_BYTES;
        __nv_bfloat16 h[16];
#pragma unroll
        for (int q = 0; q < 4; q++) {
            h[q * 4 + 0] = __float2bfloat16(xa[q].x);
            h[q * 4 + 1] = __float2bfloat16(xa[q].y);
            h[q * 4 + 2] = __float2bfloat16(xa[q].z);
            h[q * 4 + 3] = __float2bfloat16(xa[q].w);
        }
        uint32_t aoff = arow * 80 + acol * 2;
        *(uint4*)(base + aoff)      = *(uint4*)&h[0];
        *(uint4*)(base + aoff + 16) = *(uint4*)&h[8];
    };

    float acc[4][8][4];
#pragma unroll
    for (int i = 0; i < 4; i++)
#pragma unroll
        for (int j = 0; j < 8; j++)
#pragma unroll
            for (int e = 0; e < 4; e++) acc[i][j][e] = 0.f;

    const int lm = lane & 7, sel = lane >> 3;
    const uint32_t a_row_off = (uint32_t)(wm * 64 + (sel & 1) * 8 + lm) * 80 + (uint32_t)(sel >> 1) * 16;
    const uint32_t b_row_off = (uint32_t)(wn * 64 + (sel >> 1) * 8 + lm) * 80 + (uint32_t)(sel & 1) * 16;

    // prologue
    cpB(0, 0);
    CP_COMMIT();
    ldgA(0);
    stsA(0);
    CP_WAIT0();
    __syncthreads();

    for (int c = 0; c < nc; c++) {
        const int st = c & 1;
        if (c + 1 < nc) {
            cpB(c + 1, st ^ 1);
            CP_COMMIT();
            ldgA(c + 1);
        }

        const uint32_t stage = sb + st * STAGE_BYTES;
#pragma unroll
        for (int kk = 0; kk < 2; kk++) {
            const uint32_t kb = (uint32_t)kk * 32;
            uint32_t a[4][4];
#pragma unroll
            for (int mt = 0; mt < 4; mt++)
                ldm_x4(stage + a_row_off + (uint32_t)mt * (16 * 80) + kb, a[mt]);
            uint32_t b[8][2];
#pragma unroll
            for (int pr = 0; pr < 4; pr++) {
                uint32_t r[4];
                ldm_x4(stage + A_BYTES + b_row_off + (uint32_t)pr * (16 * 80) + kb, r);
                b[2 * pr][0] = r[0]; b[2 * pr][1] = r[1];
                b[2 * pr + 1][0] = r[2]; b[2 * pr + 1][1] = r[3];
            }
#pragma unroll
            for (int mt = 0; mt < 4; mt++)
#pragma unroll
                for (int nt = 0; nt < 8; nt++) mma_bf16(acc[mt][nt], a[mt], b[nt]);
        }
        if (c + 1 < nc) stsA(st ^ 1);
        CP_WAIT0();
        __syncthreads();
    }

    // epilogue
#pragma unroll
    for (int mt = 0; mt < 4; mt++) {
        int r0 = mo + wm * 64 + mt * 16 + (lane >> 2);
#pragma unroll
        for (int nt = 0; nt < 8; nt++) {
            int cb = wn * 64 + nt * 8 + (lane & 3) * 2;
            float2 v0 = make_float2(acc[mt][nt][0], acc[mt][nt][1]);
            float2 v1 = make_float2(acc[mt][nt][2], acc[mt][nt][3]);
            *(float2*)(C + (size_t)r0 * HID + cb)       = v0;
            *(float2*)(C + (size_t)(r0 + 8) * HID + cb) = v1;
        }
    }
}

// ---------------- degree / CSR construction ----------------
__global__ void k_init_deg() {
    int i = blockIdx.x * blockDim.x + threadIdx.x;
    if (i < NN) g_deg[i] = 1;
}
__global__ void k_count_deg(const int* __restrict__ dst, int E) {
    int i = blockIdx.x * blockDim.x + threadIdx.x;
    if (i < E) atomicAdd(&g_deg[dst[i]], 1);
}
__global__ void k_dinv() {
    int i = blockIdx.x * blockDim.x + threadIdx.x;
    if (i < NN) g_dinv[i] = rsqrtf((float)g_deg[i]);
}
__global__ void k_scan() {
    __shared__ int sh[1024];
    int tid = threadIdx.x;
    int local[16];
    int sum = 0;
#pragma unroll
    for (int i = 0; i < 16; i++) { local[i] = g_deg[tid * 16 + i]; sum += local[i]; }
    sh[tid] = sum;
    __syncthreads();
    for (int off = 1; off < 1024; off <<= 1) {
        int v = (tid >= off) ? sh[tid - off] : 0;
        __syncthreads();
        sh[tid] += v;
        __syncthreads();
    }
    int run = (tid == 0) ? 0 : sh[tid - 1];
#pragma unroll
    for (int i = 0; i < 16; i++) {
        g_rowstart[tid * 16 + i] = run;
        g_cursor[tid * 16 + i]   = run;
        run += local[i];
    }
    if (tid == 1023) g_rowstart[NN] = run;
}
__global__ void k_fill(const int* __restrict__ src, const int* __restrict__ dst, int E) {
    int i = blockIdx.x * blockDim.x + threadIdx.x;
    if (i >= E + NN) return;
    int s, d;
    if (i < E) { s = src[i]; d = dst[i]; }
    else       { s = i - E; d = s; }
    int slot = atomicAdd(&g_cursor[d], 1);
    g_csr[slot] = s;
}
__global__ void k_sort_rows() {
    __shared__ int s[1024];
    int r = blockIdx.x;
    int beg = g_rowstart[r], end = g_rowstart[r + 1];
    int len = end - beg;
    if (len <= 1 || len > 1024) return;
    for (int i = threadIdx.x; i < len; i += blockDim.x) s[i] = g_csr[beg + i];
    __syncthreads();
    for (int ph = 0; ph < len; ph++) {
        int off = ph & 1;
        for (int j = off + 2 * (int)threadIdx.x; j + 1 < len; j += 2 * (int)blockDim.x) {
            int a = s[j], b = s[j + 1];
            if (a > b) { s[j] = b; s[j + 1] = a; }
        }
        __syncthreads();
    }
    for (int i = threadIdx.x; i < len; i += blockDim.x) g_csr[beg + i] = s[i];
}

// ---------------- aggregation ----------------
__global__ void k_agg(const float* __restrict__ hin, float* __restrict__ hout,
                      const float* __restrict__ bias) {
    int v = blockIdx.x;
    int t = threadIdx.x;
    int beg = g_rowstart[v], end = g_rowstart[v + 1];
    float dv = g_dinv[v];
    __shared__ int   ssrc[256];
    __shared__ float snorm[256];
    float acc = 0.f;
    for (int base = beg; base < end; base += 256) {
        int n = min(256, end - base);
        if (t < n) {
            int s = g_csr[base + t];
            ssrc[t]  = s * HID;
            snorm[t] = g_dinv[s] * dv;
        }
        __syncthreads();
        int j = 0;
        for (; j + 4 <= n; j += 4) {
            float x0 = hin[ssrc[j]     + t];
            float x1 = hin[ssrc[j + 1] + t];
            float x2 = hin[ssrc[j + 2] + t];
            float x3 = hin[ssrc[j + 3] + t];
            acc += x0 * snorm[j] + x1 * snorm[j + 1] + x2 * snorm[j + 2] + x3 * snorm[j + 3];
        }
        for (; j < n; j++) acc += hin[ssrc[j] + t] * snorm[j];
        __syncthreads();
    }
    float r = acc + bias[t];
    hout[(size_t)v * HID + t] = r > 0.f ? r : 0.f;
}

// ---------------- edge scoring ----------------
__global__ void k_scores(const float* __restrict__ linW) {
    int v = blockIdx.x, t = threadIdx.x;
    float hv = g_h2[(size_t)v * HID + t];
    __shared__ float sa[256], sb2[256];
    sa[t]  = hv * linW[t];
    sb2[t] = hv * linW[HID + t];
    __syncthreads();
    for (int s = 128; s > 0; s >>= 1) {
        if (t < s) { sa[t] += sa[t + s]; sb2[t] += sb2[t + s]; }
        __syncthreads();
    }
    if (t == 0) { g_sa[v] = sa[0]; g_sb[v] = sb2[0]; }
}
__global__ void k_edge_out(const int* __restrict__ src, const int* __restrict__ dst,
                           const float* __restrict__ linb, float* __restrict__ out, int E) {
    int i = blockIdx.x * blockDim.x + threadIdx.x;
    if (i < E) out[i] = g_sa[src[i]] + g_sb[dst[i]] + linb[0];
}

// ---------------- launch ----------------
extern "C" void kernel_launch(void* const* d_in, const int* in_sizes, int n_in,
                              void* d_out, int out_size) {
    const float* x    = (const float*)d_in[0];
    const int*   ei   = (const int*)d_in[1];
    const float* W1   = (const float*)d_in[2];
    const float* b1   = (const float*)d_in[3];
    const float* W2   = (const float*)d_in[4];
    const float* b2   = (const float*)d_in[5];
    const float* linW = (const float*)d_in[6];
    const float* linb = (const float*)d_in[7];
    float* out = (float*)d_out;

    int E = in_sizes[1] / 2;
    const int* esrc = ei;
    const int* edst = ei + E;

    float *h1, *h2;
    __nv_bfloat16 *B1, *B2;
    cudaGetSymbolAddress((void**)&h1, g_h1);
    cudaGetSymbolAddress((void**)&h2, g_h2);
    cudaGetSymbolAddress((void**)&B1, g_B1);
    cudaGetSymbolAddress((void**)&B2, g_B2);

    cudaFuncSetAttribute(k_hgemm, cudaFuncAttributeMaxDynamicSharedMemorySize, HG_SMEM);

    // launch order arranged so k_hgemm (layer 1) is launch index 3 -> ncu captures it
    k_prep_B<<<dim3(NN / 32, HID / 32), 256>>>(W1, B1, NN);        // 0
    k_prep_B<<<dim3(HID / 32, HID / 32), 256>>>(W2, B2, HID);      // 1
    k_init_deg<<<NN / 256, 256>>>();                               // 2
    k_hgemm<<<NN / 128, 256, HG_SMEM>>>(x, B1, h1, NN);            // 3 <- profile target

    // graph structure
    k_count_deg<<<(E + 255) / 256, 256>>>(edst, E);
    k_dinv<<<NN / 256, 256>>>();
    k_scan<<<1, 1024>>>();
    k_fill<<<(E + NN + 255) / 256, 256>>>(esrc, edst, E);
    k_sort_rows<<<NN, 256>>>();

    // layer 1 aggregation
    k_agg<<<NN, 256>>>(h1, h2, b1);
    // layer 2
    k_hgemm<<<NN / 128, 256, HG_SMEM>>>(h2, B2, h1, HID);
    k_agg<<<NN, 256>>>(h1, h2, b2);

    // edge scores
    k_scores<<<NN, 256>>>(linW);
    k_edge_out<<<(E + 255) / 256, 256>>>(esrc, edst, linb, out, E);
}